// round 4
// baseline (speedup 1.0000x reference)
#include <cuda_runtime.h>
#include <cuda_bf16.h>
#include <math.h>
#include <stdint.h>

#define B_   64
#define FULLN 513
#define E_   768
#define NB   32
#define H_   12
#define HD   64
#define BH   (B_ * H_)        // 768
#define E4   (E_ / 4)         // 192
#define KE   2304             // extended K = 3 * 768

// -------- scratch (device globals; no allocation allowed) --------
__device__ float g_sampled[B_ * NB * E_];   // (2048, 768)
__device__ float g_q[B_ * E_];              // (64, 768)
__device__ float g_T[BH * E_];              // (768, 768)
__device__ float g_TK[BH * E_];             // (768, 768)
__device__ float g_attn[BH * NB];           // (768, 32)
__device__ float g_US[BH * E_];             // (768, 768)
__device__ float g_U[BH * E_];              // (768, 768)
__device__ float g_ctx[B_ * E_];            // (64, 768)
__device__ float g_ao[B_ * E_];             // (64, 768)
__device__ float g_part[4 * BH * E_];       // split-K partials (small gemms)

// extended bf16 operands for tensor-core GEMMs: [hi, lo, hi] x [hi, hi, lo]
__device__ __nv_bfloat16 g_bAext[E_ * KE];   // activations (T or US)
__device__ __nv_bfloat16 g_bWext[E_ * KE];   // Ws rows-as-n  (for U = US @ Ws.T)
__device__ __nv_bfloat16 g_bWtext[E_ * KE];  // Ws^T rows-as-n (for TK = T @ Ws)

// ================= mma.sync helpers (baseline PTX, sm_80+) =================
__device__ __forceinline__ uint32_t smem_u32(const void* p) {
    uint32_t a;
    asm("{ .reg .u64 t; cvta.to.shared.u64 t, %1; cvt.u32.u64 %0, t; }" : "=r"(a) : "l"(p));
    return a;
}
__device__ __forceinline__ void ldsm_x4(uint32_t addr, uint32_t& r0, uint32_t& r1,
                                        uint32_t& r2, uint32_t& r3) {
    asm volatile("ldmatrix.sync.aligned.m8n8.x4.shared.b16 {%0,%1,%2,%3}, [%4];"
                 : "=r"(r0), "=r"(r1), "=r"(r2), "=r"(r3) : "r"(addr));
}
__device__ __forceinline__ void mma16816(float* d, const uint32_t* a, const uint32_t* b) {
    asm volatile("mma.sync.aligned.m16n8k16.row.col.f32.bf16.bf16.f32 "
                 "{%0,%1,%2,%3}, {%4,%5,%6,%7}, {%8,%9}, {%0,%1,%2,%3};"
                 : "+f"(d[0]), "+f"(d[1]), "+f"(d[2]), "+f"(d[3])
                 : "r"(a[0]), "r"(a[1]), "r"(a[2]), "r"(a[3]), "r"(b[0]), "r"(b[1]));
}

// ================= bf16 HMMA GEMM =================
// C[m,n] = sum_{k<KE} Aext[m,k] * Bext[n,k]  (+ bias[n])
// M = N = 768.  CTA tile 64x64, 8 warps (warp tile 32x16), K-chunk 32,
// double-buffered smem, 80B-padded rows (conflict-free ldmatrix).
#define CH    32
#define NCHNK (KE / CH)        // 72
#define ROWB  80
#define TILEB (64 * ROWB)      // 5120
#define BUFB  (2 * TILEB)      // 10240

__global__ void __launch_bounds__(256) mma_gemm_kernel(
    const __nv_bfloat16* __restrict__ Aext, const __nv_bfloat16* __restrict__ Bext,
    const float* __restrict__ bias, float* __restrict__ C)
{
    __shared__ __align__(16) char smem[2 * BUFB];   // 20480 B
    const int tid = threadIdx.x;
    const int w = tid >> 5, lane = tid & 31;
    const int m0 = blockIdx.y * 64;
    const int n0 = blockIdx.x * 64;
    const int wm = w & 1, wn = w >> 1;   // 2 x 4 warp grid

    const uint32_t sbase = smem_u32(smem);

    // ---- global->smem staging mapping: thread t -> row t/4, 16B segment t%4 ----
    const int row = tid >> 2, seg = tid & 3;
    const __nv_bfloat16* gA = Aext + (long)(m0 + row) * KE + seg * 8;
    const __nv_bfloat16* gB = Bext + (long)(n0 + row) * KE + seg * 8;
    const uint32_t stOff = row * ROWB + seg * 16;

    float acc[2][2][4];
#pragma unroll
    for (int i = 0; i < 2; i++)
#pragma unroll
        for (int j = 0; j < 2; j++)
#pragma unroll
            for (int v = 0; v < 4; v++) acc[i][j][v] = 0.f;

    // ---- prologue: chunk 0 into buf0, stage chunk 1 in regs ----
    {
        uint4 a0 = *(const uint4*)gA;
        uint4 b0 = *(const uint4*)gB;
        *(uint4*)(smem + stOff) = a0;
        *(uint4*)(smem + TILEB + stOff) = b0;
    }
    uint4 ra = *(const uint4*)(gA + CH);
    uint4 rb = *(const uint4*)(gB + CH);
    __syncthreads();

    // ---- ldmatrix lane address offsets ----
    const int qq = lane >> 3, r8 = lane & 7;
    // A x4: quadrants (m0-7,k0-7),(m8-15,k0-7),(m0-7,k8-15),(m8-15,k8-15)
    const uint32_t aoff = (uint32_t)((wm * 32 + (qq & 1) * 8 + r8) * ROWB + ((qq >> 1) * 8) * 2);
    // B x4: quadrants (n0-7,k0-7),(n0-7,k8-15),(n8-15,k0-7),(n8-15,k8-15)
    const uint32_t boff = (uint32_t)(TILEB + (wn * 16 + (qq >> 1) * 8 + r8) * ROWB + ((qq & 1) * 8) * 2);

    for (int c = 0; c < NCHNK; c++) {
        const uint32_t base = sbase + (c & 1) * BUFB;
#pragma unroll
        for (int s = 0; s < 2; s++) {           // two k16 steps per chunk
            uint32_t af0[4], af1[4], bf[4];
            ldsm_x4(base + boff + s * 32, bf[0], bf[1], bf[2], bf[3]);
            ldsm_x4(base + aoff + s * 32, af0[0], af0[1], af0[2], af0[3]);
            ldsm_x4(base + aoff + 16 * ROWB + s * 32, af1[0], af1[1], af1[2], af1[3]);
            mma16816(acc[0][0], af0, bf + 0);
            mma16816(acc[0][1], af0, bf + 2);
            mma16816(acc[1][0], af1, bf + 0);
            mma16816(acc[1][1], af1, bf + 2);
        }
        if (c + 1 < NCHNK) {
            char* d = smem + ((c + 1) & 1) * BUFB;
            *(uint4*)(d + stOff) = ra;
            *(uint4*)(d + TILEB + stOff) = rb;
            if (c + 2 < NCHNK) {
                ra = *(const uint4*)(gA + (c + 2) * CH);
                rb = *(const uint4*)(gB + (c + 2) * CH);
            }
        }
        __syncthreads();
    }

    // ---- epilogue ----
    const int gr = lane >> 2, gc = (lane & 3) * 2;
#pragma unroll
    for (int mi = 0; mi < 2; mi++) {
#pragma unroll
        for (int ni = 0; ni < 2; ni++) {
            int rr = m0 + wm * 32 + mi * 16 + gr;
            int cc = n0 + wn * 16 + ni * 8 + gc;
            float bx = 0.f, by = 0.f;
            if (bias) { bx = bias[cc]; by = bias[cc + 1]; }
            float2 v0 = make_float2(acc[mi][ni][0] + bx, acc[mi][ni][1] + by);
            float2 v1 = make_float2(acc[mi][ni][2] + bx, acc[mi][ni][3] + by);
            *(float2*)(C + (long)rr * E_ + cc) = v0;
            *(float2*)(C + (long)(rr + 8) * E_ + cc) = v1;
        }
    }
}

// ================= fp32 -> extended bf16 converters =================
// modeB=0 (activations): segments (hi, lo, hi); modeB=1 (weights): (hi, hi, lo)
__global__ void __launch_bounds__(256) convert_ext_kernel(
    const float* __restrict__ in, __nv_bfloat16* __restrict__ out, int total, int modeB)
{
    int i = blockIdx.x * blockDim.x + threadIdx.x;
    if (i >= total) return;
    int rr = i / E_, cc = i % E_;
    float x = in[i];
    __nv_bfloat16 h = __float2bfloat16(x);
    __nv_bfloat16 l = __float2bfloat16(x - __bfloat162float(h));
    __nv_bfloat16* o = out + (long)rr * KE + cc;
    o[0] = h;
    o[E_] = modeB ? h : l;
    o[2 * E_] = modeB ? l : h;
}

// transposed weight ext: out row n = Ws[:,n], segments (hi, hi, lo)
__global__ void __launch_bounds__(256) transpose_ext_kernel(
    const float* __restrict__ in, __nv_bfloat16* __restrict__ out)
{
    __shared__ float tile[32][33];
    int tx = threadIdx.x & 31, ty = threadIdx.x >> 5;  // 32 x 8
    int bx = blockIdx.x * 32, by = blockIdx.y * 32;
#pragma unroll
    for (int j = 0; j < 4; j++)
        tile[ty + 8 * j][tx] = in[(long)(by + ty + 8 * j) * E_ + bx + tx];
    __syncthreads();
#pragma unroll
    for (int j = 0; j < 4; j++) {
        float x = tile[tx][ty + 8 * j];
        __nv_bfloat16 h = __float2bfloat16(x);
        __nv_bfloat16 l = __float2bfloat16(x - __bfloat162float(h));
        __nv_bfloat16* o = out + (long)(bx + ty + 8 * j) * KE + by + tx;
        o[0] = h;
        o[E_] = h;
        o[2 * E_] = l;
    }
}

// ================= trilinear sample =================
__global__ void __launch_bounds__(192) sample_kernel(
    const float* __restrict__ x, const float* __restrict__ base,
    const float* __restrict__ off, float* __restrict__ out)
{
    int bp = blockIdx.x;
    int b = bp >> 5, p = bp & 31;

    float cx = fminf(fmaxf(base[p * 3 + 0] + off[bp * 3 + 0], -1.f), 1.f);
    float cy = fminf(fmaxf(base[p * 3 + 1] + off[bp * 3 + 1], -1.f), 1.f);
    float cz = fminf(fmaxf(base[p * 3 + 2] + off[bp * 3 + 2], -1.f), 1.f);

    float ix = (cx + 1.f) * 3.5f;
    float iy = (cy + 1.f) * 3.5f;
    float iz = (cz + 1.f) * 3.5f;
    float fx = floorf(ix), fy = floorf(iy), fz = floorf(iz);
    float wx = ix - fx, wy = iy - fy, wz = iz - fz;
    int x0 = max(0, min(7, (int)fx));
    int y0 = max(0, min(7, (int)fy));
    int z0 = max(0, min(7, (int)fz));
    int x1 = min(7, x0 + 1), y1 = min(7, y0 + 1), z1 = min(7, z0 + 1);

    int r000 = 1 + ((z0 * 8 + y0) * 8 + x0);
    int r001 = 1 + ((z0 * 8 + y0) * 8 + x1);
    int r010 = 1 + ((z0 * 8 + y1) * 8 + x0);
    int r011 = 1 + ((z0 * 8 + y1) * 8 + x1);
    int r100 = 1 + ((z1 * 8 + y0) * 8 + x0);
    int r101 = 1 + ((z1 * 8 + y0) * 8 + x1);
    int r110 = 1 + ((z1 * 8 + y1) * 8 + x0);
    int r111 = 1 + ((z1 * 8 + y1) * 8 + x1);

    float w000 = (1.f - wz) * (1.f - wy) * (1.f - wx);
    float w001 = (1.f - wz) * (1.f - wy) * wx;
    float w010 = (1.f - wz) * wy * (1.f - wx);
    float w011 = (1.f - wz) * wy * wx;
    float w100 = wz * (1.f - wy) * (1.f - wx);
    float w101 = wz * (1.f - wy) * wx;
    float w110 = wz * wy * (1.f - wx);
    float w111 = wz * wy * wx;

    const float4* X = reinterpret_cast<const float4*>(x) + (long)b * FULLN * E4;
    int t = threadIdx.x;
    float4 s = make_float4(0.f, 0.f, 0.f, 0.f);
#define ACC(R, W) { float4 v = X[(R) * E4 + t]; \
        s.x = fmaf(W, v.x, s.x); s.y = fmaf(W, v.y, s.y); \
        s.z = fmaf(W, v.z, s.z); s.w = fmaf(W, v.w, s.w); }
    ACC(r000, w000) ACC(r001, w001) ACC(r010, w010) ACC(r011, w011)
    ACC(r100, w100) ACC(r101, w101) ACC(r110, w110) ACC(r111, w111)
#undef ACC
    reinterpret_cast<float4*>(out)[(long)bp * E4 + t] = s;
}

// ================= SIMT GEMM (small matrices) =================
template <bool TB>
__global__ void __launch_bounds__(256) sgemm_kernel(
    const float* __restrict__ A, const float* __restrict__ Bm,
    const float* __restrict__ bias, float* __restrict__ C,
    int kChunk, int lda, int ldb, int ldc,
    int sAz, int sBz, int sCz, int sBiasz,
    int nSplit, long sCsplit)
{
    __shared__ __align__(16) float As[16][68];
    __shared__ __align__(16) float Bs[16][68];
    const int tid = threadIdx.x;
    const int m0 = blockIdx.y * 64;
    const int n0 = blockIdx.x * 64;

    const int zb = blockIdx.z / nSplit;
    const int sp = blockIdx.z - zb * nSplit;

    A  += (long)zb * sAz + sp * kChunk;
    if (TB) Bm += (long)zb * sBz + sp * kChunk;
    else    Bm += (long)zb * sBz + (long)sp * kChunk * ldb;
    C  += (long)zb * sCz + (long)sp * sCsplit;
    const int biasOff = zb * sBiasz;

    const int ra = tid >> 2;
    const int ka = (tid & 3) << 2;
    const int ty = tid >> 4;
    const int tx = tid & 15;

    float acc[4][4];
#pragma unroll
    for (int i = 0; i < 4; i++)
#pragma unroll
        for (int j = 0; j < 4; j++) acc[i][j] = 0.f;

    for (int k0 = 0; k0 < kChunk; k0 += 16) {
        float4 a4 = *reinterpret_cast<const float4*>(&A[(long)(m0 + ra) * lda + k0 + ka]);
        As[ka + 0][ra] = a4.x; As[ka + 1][ra] = a4.y;
        As[ka + 2][ra] = a4.z; As[ka + 3][ra] = a4.w;
        if (TB) {
            float4 b4 = *reinterpret_cast<const float4*>(&Bm[(long)(n0 + ra) * ldb + k0 + ka]);
            Bs[ka + 0][ra] = b4.x; Bs[ka + 1][ra] = b4.y;
            Bs[ka + 2][ra] = b4.z; Bs[ka + 3][ra] = b4.w;
        } else {
            const int kb = tid >> 4;
            const int nb = (tid & 15) << 2;
            float4 b4 = *reinterpret_cast<const float4*>(&Bm[(long)(k0 + kb) * ldb + n0 + nb]);
            Bs[kb][nb + 0] = b4.x; Bs[kb][nb + 1] = b4.y;
            Bs[kb][nb + 2] = b4.z; Bs[kb][nb + 3] = b4.w;
        }
        __syncthreads();
#pragma unroll
        for (int kk = 0; kk < 16; kk++) {
            float4 av = *reinterpret_cast<const float4*>(&As[kk][ty * 4]);
            float4 bv = *reinterpret_cast<const float4*>(&Bs[kk][tx * 4]);
            float a[4] = {av.x, av.y, av.z, av.w};
            float b[4] = {bv.x, bv.y, bv.z, bv.w};
#pragma unroll
            for (int i = 0; i < 4; i++)
#pragma unroll
                for (int j = 0; j < 4; j++)
                    acc[i][j] = fmaf(a[i], b[j], acc[i][j]);
        }
        __syncthreads();
    }

#pragma unroll
    for (int i = 0; i < 4; i++) {
        int m = m0 + ty * 4 + i;
#pragma unroll
        for (int j = 0; j < 4; j++) {
            int n = n0 + tx * 4 + j;
            float v = acc[i][j];
            if (nSplit == 1 && bias) v += bias[biasOff + n];
            C[(long)m * ldc + n] = v;
        }
    }
}

__global__ void __launch_bounds__(256) reduce_kernel(
    const float* __restrict__ part, const float* __restrict__ bias,
    float* __restrict__ C, int total4, int nSplit, int ldc4)
{
    int i = blockIdx.x * blockDim.x + threadIdx.x;
    if (i >= total4) return;
    const float4* P = reinterpret_cast<const float4*>(part);
    float4 s = P[i];
    for (int sp = 1; sp < nSplit; sp++) {
        float4 v = P[(long)sp * total4 + i];
        s.x += v.x; s.y += v.y; s.z += v.z; s.w += v.w;
    }
    if (bias) {
        float4 b = reinterpret_cast<const float4*>(bias)[i % ldc4];
        s.x += b.x; s.y += b.y; s.z += b.z; s.w += b.w;
    }
    reinterpret_cast<float4*>(C)[i] = s;
}

// ================= scores + softmax =================
__global__ void __launch_bounds__(128) scores_softmax_kernel(
    const float* __restrict__ TK, const float* __restrict__ T,
    const float* __restrict__ q, const float* __restrict__ sampled,
    const float* __restrict__ in_proj_b, const float* __restrict__ bs,
    float* __restrict__ attn)
{
    int bh = blockIdx.x;
    int b = bh / H_, h = bh % H_;
    __shared__ float tk[E_];
    __shared__ float sc[NB];
    __shared__ float red[4];
    __shared__ float cbs;
    int tid = threadIdx.x;
    int w = tid >> 5, lane = tid & 31;

    const float* TKrow = TK + (long)bh * E_;
    const float* Trow  = T + (long)bh * E_;
    float part = 0.f;
    for (int f = tid; f < E_; f += 128) {
        float t = TKrow[f];
        tk[f] = t;
        part += Trow[f] * bs[f];
    }
    if (tid < HD)
        part += q[(long)b * E_ + h * HD + tid] * in_proj_b[E_ + h * HD + tid];
#pragma unroll
    for (int o = 16; o; o >>= 1) part += __shfl_xor_sync(0xffffffffu, part, o);
    if (lane == 0) red[w] = part;
    __syncthreads();
    if (tid == 0) cbs = red[0] + red[1] + red[2] + red[3];
    __syncthreads();

    float cb = cbs;
#pragma unroll
    for (int pi = 0; pi < 8; pi++) {
        int p = w * 8 + pi;
        const float* srow = sampled + ((long)b * NB + p) * E_;
        float d = 0.f;
        for (int f = lane; f < E_; f += 32) d = fmaf(tk[f], srow[f], d);
#pragma unroll
        for (int o = 16; o; o >>= 1) d += __shfl_xor_sync(0xffffffffu, d, o);
        if (lane == 0) sc[p] = (d + cb) * 0.125f;
    }
    __syncthreads();
    if (tid < NB) {
        float s = sc[tid];
        float m = s;
#pragma unroll
        for (int o = 16; o; o >>= 1) m = fmaxf(m, __shfl_xor_sync(0xffffffffu, m, o));
        float e = expf(s - m);
        float sum = e;
#pragma unroll
        for (int o = 16; o; o >>= 1) sum += __shfl_xor_sync(0xffffffffu, sum, o);
        attn[(long)bh * NB + tid] = e / sum;
    }
}

// ================= US =================
__global__ void __launch_bounds__(192) us_kernel(
    const float* __restrict__ attn, const float* __restrict__ sampled,
    float* __restrict__ US)
{
    int bh = blockIdx.x;
    int b = bh / H_;
    __shared__ float a[NB];
    if (threadIdx.x < NB) a[threadIdx.x] = attn[(long)bh * NB + threadIdx.x];
    __syncthreads();
    int t = threadIdx.x;
    const float4* S = reinterpret_cast<const float4*>(sampled) + (long)b * NB * E4;
    float4 acc = make_float4(0.f, 0.f, 0.f, 0.f);
#pragma unroll 8
    for (int p = 0; p < NB; p++) {
        float wv = a[p];
        float4 s = S[p * E4 + t];
        acc.x = fmaf(wv, s.x, acc.x); acc.y = fmaf(wv, s.y, acc.y);
        acc.z = fmaf(wv, s.z, acc.z); acc.w = fmaf(wv, s.w, acc.w);
    }
    reinterpret_cast<float4*>(US)[(long)bh * E4 + t] = acc;
}

// ================= broadcast out =================
__global__ void __launch_bounds__(256) out_kernel(
    const float* __restrict__ ao, const float* __restrict__ conf,
    float4* __restrict__ out)
{
    const int total = B_ * FULLN * E4;
    int i = blockIdx.x * blockDim.x + threadIdx.x;
    if (i >= total) return;
    int b = i / (FULLN * E4);
    int c4 = i % E4;
    float s = conf[b];
    float4 v = reinterpret_cast<const float4*>(ao)[b * E4 + c4];
    v.x *= s; v.y *= s; v.z *= s; v.w *= s;
    out[i] = v;
}

// ================================================================
extern "C" void kernel_launch(void* const* d_in, const int* in_sizes, int n_in,
                              void* d_out, int out_size)
{
    const float* x    = (const float*)d_in[0];
    const float* bio  = (const float*)d_in[1];
    const float* base = (const float*)d_in[2];
    const float* off  = (const float*)d_in[3];
    const float* conf = (const float*)d_in[4];
    const float* Ws   = (const float*)d_in[5];
    const float* bs   = (const float*)d_in[6];
    const float* Win  = (const float*)d_in[7];
    const float* bin  = (const float*)d_in[8];
    const float* Wo   = (const float*)d_in[9];
    const float* bo   = (const float*)d_in[10];
    float* out = (float*)d_out;

    float *sampled, *q, *T, *TK, *attn, *US, *U, *ctx, *ao, *part;
    cudaGetSymbolAddress((void**)&sampled, g_sampled);
    cudaGetSymbolAddress((void**)&q,   g_q);
    cudaGetSymbolAddress((void**)&T,   g_T);
    cudaGetSymbolAddress((void**)&TK,  g_TK);
    cudaGetSymbolAddress((void**)&attn,g_attn);
    cudaGetSymbolAddress((void**)&US,  g_US);
    cudaGetSymbolAddress((void**)&U,   g_U);
    cudaGetSymbolAddress((void**)&ctx, g_ctx);
    cudaGetSymbolAddress((void**)&ao,  g_ao);
    cudaGetSymbolAddress((void**)&part,g_part);

    __nv_bfloat16 *bAext, *bWext, *bWtext;
    cudaGetSymbolAddress((void**)&bAext,  g_bAext);
    cudaGetSymbolAddress((void**)&bWext,  g_bWext);
    cudaGetSymbolAddress((void**)&bWtext, g_bWtext);

    const int smallT4 = 64 * E_ / 4;
    const int nElems  = E_ * E_;

    // 1) trilinear sample
    sample_kernel<<<B_ * NB, 192>>>(x, base, off, sampled);

    // weight conversions (independent)
    convert_ext_kernel<<<(nElems + 255) / 256, 256>>>(Ws, bWext, nElems, 1);
    transpose_ext_kernel<<<dim3(24, 24), 256>>>(Ws, bWtext);

    // 2) q = bio @ Wq.T + bq  (split-K=8)
    sgemm_kernel<true><<<dim3(12, 1, 8), 256>>>(
        bio, Win, nullptr, part, 96, E_, E_, E_, 0, 0, 0, 0, 8, (long)64 * E_);
    reduce_kernel<<<(smallT4 + 255) / 256, 256>>>(part, bin, q, smallT4, 8, E4);

    // 3) T_h = q_h @ Wk_h  (per head)
    sgemm_kernel<false><<<dim3(12, 1, H_), 256>>>(
        q, Win + E_ * E_, nullptr, T, HD,
        E_, E_, H_ * E_, HD, HD * E_, E_, 0, 1, 0);

    // 4) TK = T @ Ws  (HMMA): B row n = Ws[:,n]
    convert_ext_kernel<<<(nElems + 255) / 256, 256>>>(T, bAext, nElems, 0);
    mma_gemm_kernel<<<dim3(12, 12), 256>>>(bAext, bWtext, nullptr, TK);

    // 5) scores + softmax
    scores_softmax_kernel<<<BH, 128>>>(TK, T, q, sampled, bin, bs, attn);

    // 6) US
    us_kernel<<<BH, 192>>>(attn, sampled, US);

    // 7) U = US @ Ws.T + bs  (HMMA): B row n = Ws[n,:]
    convert_ext_kernel<<<(nElems + 255) / 256, 256>>>(US, bAext, nElems, 0);
    mma_gemm_kernel<<<dim3(12, 12), 256>>>(bAext, bWext, bs, U);

    // 8) ctx_h = U_h @ Wv_h.T + bv_h  (split-K=8)
    sgemm_kernel<true><<<dim3(1, 1, H_ * 8), 256>>>(
        U, Win + 2 * E_ * E_, nullptr, part, 96,
        H_ * E_, E_, E_, E_, HD * E_, HD, HD, 8, (long)64 * E_);
    reduce_kernel<<<(smallT4 + 255) / 256, 256>>>(part, bin + 2 * E_, ctx, smallT4, 8, E4);

    // 9) attn_out = ctx @ Wo.T + bo  (split-K=8)
    sgemm_kernel<true><<<dim3(12, 1, 8), 256>>>(
        ctx, Wo, nullptr, part, 96, E_, E_, E_, 0, 0, 0, 0, 8, (long)64 * E_);
    reduce_kernel<<<(smallT4 + 255) / 256, 256>>>(part, bo, ao, smallT4, 8, E4);

    // 10) broadcast * confidence
    out_kernel<<<(B_ * FULLN * E4 + 255) / 256, 256>>>(ao, conf, (float4*)out);
}

// round 6
// speedup vs baseline: 1.0315x; 1.0315x over previous
#include <cuda_runtime.h>
#include <cuda_bf16.h>
#include <math.h>
#include <stdint.h>

#define B_    64
#define FULLN 513
#define E_    768
#define NB    32
#define H_    12
#define HD    64
#define BH    (B_ * H_)       // 768
#define E4    (E_ / 4)        // 192
#define KE    2304            // extended K = 3 * 768

// -------- scratch (device globals; no allocation allowed) --------
__device__ float g_sampled[B_ * NB * E_];
__device__ float g_q[B_ * E_];
__device__ float g_T[BH * E_];
__device__ float g_TK[BH * E_];
__device__ float g_attn[BH * NB];
__device__ float g_ao[B_ * E_];
__device__ float g_part[4 * B_ * E_];        // split-K partials (skinny gemms)

// bf16 extended operands.  A-mode segments: (hi, lo, hi); B-mode: (hi, hi, lo)
__device__ __nv_bfloat16 g_ext1[E_ * KE];    // T-ext, then US-ext (A-mode, reused)
__device__ __nv_bfloat16 g_Uext[E_ * KE];    // U-ext (A-mode)
__device__ __nv_bfloat16 g_Wsext[E_ * KE];   // Ws rows       (B-mode)
__device__ __nv_bfloat16 g_Wstext[E_ * KE];  // Ws^T rows     (B-mode)
__device__ __nv_bfloat16 g_Wq[E_ * KE];      // Wq rows (B-mode)
__device__ __nv_bfloat16 g_Wv[E_ * KE];      // Wv rows (B-mode)
__device__ __nv_bfloat16 g_Wo[E_ * KE];      // Wo rows (B-mode)
__device__ __nv_bfloat16 g_bioext[B_ * KE];  // bio (A-mode)
__device__ __nv_bfloat16 g_ctxext[B_ * KE];  // ctx (A-mode)

// ================= mma.sync helpers (baseline PTX, sm_80+) =================
__device__ __forceinline__ uint32_t smem_u32(const void* p) {
    uint32_t a;
    asm("{ .reg .u64 t; cvta.to.shared.u64 t, %1; cvt.u32.u64 %0, t; }" : "=r"(a) : "l"(p));
    return a;
}
__device__ __forceinline__ void ldsm_x4(uint32_t addr, uint32_t& r0, uint32_t& r1,
                                        uint32_t& r2, uint32_t& r3) {
    asm volatile("ldmatrix.sync.aligned.m8n8.x4.shared.b16 {%0,%1,%2,%3}, [%4];"
                 : "=r"(r0), "=r"(r1), "=r"(r2), "=r"(r3) : "r"(addr));
}
__device__ __forceinline__ void mma16816(float* d, const uint32_t* a, const uint32_t* b) {
    asm volatile("mma.sync.aligned.m16n8k16.row.col.f32.bf16.bf16.f32 "
                 "{%0,%1,%2,%3}, {%4,%5,%6,%7}, {%8,%9}, {%0,%1,%2,%3};"
                 : "+f"(d[0]), "+f"(d[1]), "+f"(d[2]), "+f"(d[3])
                 : "r"(a[0]), "r"(a[1]), "r"(a[2]), "r"(a[3]), "r"(b[0]), "r"(b[1]));
}
__device__ __forceinline__ void st_hilo_pair(__nv_bfloat16* base, float x, float y) {
    // writes hi pair at +0, lo pair at +E_, hi pair at +2*E_   (A-mode)
    __nv_bfloat16 hx = __float2bfloat16(x), hy = __float2bfloat16(y);
    __nv_bfloat16 lx = __float2bfloat16(x - __bfloat162float(hx));
    __nv_bfloat16 ly = __float2bfloat16(y - __bfloat162float(hy));
    __nv_bfloat162 hp; hp.x = hx; hp.y = hy;
    __nv_bfloat162 lp; lp.x = lx; lp.y = ly;
    *(__nv_bfloat162*)(base) = hp;
    *(__nv_bfloat162*)(base + E_) = lp;
    *(__nv_bfloat162*)(base + 2 * E_) = hp;
}

// ================= unified HMMA GEMM =================
// C[m, col] = sum_{k in split} Aext[m,k] * Bext[col,k]
//   grid = (nTiles, mTiles, nZ * nSplit);  CTA tile 64x64, 8 warps (32x16 each)
//   A row stride lda; per-z offsets sAz (A), sBz (B); col0 = n0 + zb*nOffMul.
//   nSplit>1: write partials Cp + sp*splitStride (no bias).
//   nSplit==1: optional bias; write Cout (fp32, ldc=E_) and/or extOut (A-mode).
#define CH    32
#define ROWB  80
#define TILEB (64 * ROWB)      // 5120
#define BUFB  (2 * TILEB)      // 10240

__global__ void __launch_bounds__(256) hmma_kernel(
    const __nv_bfloat16* __restrict__ Aext, long lda, long sAz,
    const __nv_bfloat16* __restrict__ Bext, long sBz,
    const float* __restrict__ bias,
    float* __restrict__ Cout, __nv_bfloat16* __restrict__ extOut,
    int nOffMul, int nSplit, int kLen, long splitStride)
{
    __shared__ __align__(16) char smem[2 * BUFB];   // 20480 B
    const int tid = threadIdx.x;
    const int w = tid >> 5, lane = tid & 31;
    const int m0 = blockIdx.y * 64;
    const int n0 = blockIdx.x * 64;
    const int zb = blockIdx.z / nSplit;
    const int sp = blockIdx.z - zb * nSplit;
    const int wm = w & 1, wn = w >> 1;

    const uint32_t sbase = smem_u32(smem);

    const int row = tid >> 2, seg = tid & 3;
    const __nv_bfloat16* gA = Aext + zb * sAz + (long)(m0 + row) * lda + sp * kLen + seg * 8;
    const __nv_bfloat16* gB = Bext + zb * sBz + (long)(n0 + row) * KE + sp * kLen + seg * 8;
    const uint32_t stOff = row * ROWB + seg * 16;

    float acc[2][2][4];
#pragma unroll
    for (int i = 0; i < 2; i++)
#pragma unroll
        for (int j = 0; j < 2; j++)
#pragma unroll
            for (int v = 0; v < 4; v++) acc[i][j][v] = 0.f;

    const int cnum = kLen / CH;
    {
        uint4 a0 = *(const uint4*)gA;
        uint4 b0 = *(const uint4*)gB;
        *(uint4*)(smem + stOff) = a0;
        *(uint4*)(smem + TILEB + stOff) = b0;
    }
    uint4 ra = *(const uint4*)(gA + CH);
    uint4 rb = *(const uint4*)(gB + CH);
    __syncthreads();

    const int qq = lane >> 3, r8 = lane & 7;
    const uint32_t aoff = (uint32_t)((wm * 32 + (qq & 1) * 8 + r8) * ROWB + ((qq >> 1) * 8) * 2);
    const uint32_t boff = (uint32_t)(TILEB + (wn * 16 + (qq >> 1) * 8 + r8) * ROWB + ((qq & 1) * 8) * 2);

    for (int c = 0; c < cnum; c++) {
        const uint32_t base = sbase + (c & 1) * BUFB;
#pragma unroll
        for (int s = 0; s < 2; s++) {
            uint32_t af0[4], af1[4], bf[4];
            ldsm_x4(base + boff + s * 32, bf[0], bf[1], bf[2], bf[3]);
            ldsm_x4(base + aoff + s * 32, af0[0], af0[1], af0[2], af0[3]);
            ldsm_x4(base + aoff + 16 * ROWB + s * 32, af1[0], af1[1], af1[2], af1[3]);
            mma16816(acc[0][0], af0, bf + 0);
            mma16816(acc[0][1], af0, bf + 2);
            mma16816(acc[1][0], af1, bf + 0);
            mma16816(acc[1][1], af1, bf + 2);
        }
        if (c + 1 < cnum) {
            char* d = smem + ((c + 1) & 1) * BUFB;
            *(uint4*)(d + stOff) = ra;
            *(uint4*)(d + TILEB + stOff) = rb;
            if (c + 2 < cnum) {
                ra = *(const uint4*)(gA + (long)(c + 2) * CH);
                rb = *(const uint4*)(gB + (long)(c + 2) * CH);
            }
        }
        __syncthreads();
    }

    // ---- epilogue ----
    float* Cp = Cout ? (Cout + sp * splitStride) : nullptr;
    const int col0 = n0 + zb * nOffMul;
    const int gr = lane >> 2, gc = (lane & 3) * 2;
#pragma unroll
    for (int mi = 0; mi < 2; mi++) {
#pragma unroll
        for (int ni = 0; ni < 2; ni++) {
            int rr = m0 + wm * 32 + mi * 16 + gr;
            int cc = col0 + wn * 16 + ni * 8 + gc;
            float bx = 0.f, by = 0.f;
            if (bias) { bx = bias[cc]; by = bias[cc + 1]; }
            float x0 = acc[mi][ni][0] + bx, y0 = acc[mi][ni][1] + by;
            float x1 = acc[mi][ni][2] + bx, y1 = acc[mi][ni][3] + by;
            if (Cp) {
                *(float2*)(Cp + (long)rr * E_ + cc) = make_float2(x0, y0);
                *(float2*)(Cp + (long)(rr + 8) * E_ + cc) = make_float2(x1, y1);
            }
            if (extOut) {
                st_hilo_pair(extOut + (long)rr * KE + cc, x0, y0);
                st_hilo_pair(extOut + (long)(rr + 8) * KE + cc, x1, y1);
            }
        }
    }
}

// ================= split-K reduce (64 x 768), optional fp32 / ext outputs ===
__global__ void __launch_bounds__(256) reduce2_kernel(
    const float* __restrict__ part, const float* __restrict__ bias,
    float* __restrict__ Cout, __nv_bfloat16* __restrict__ extOut, int nSplit)
{
    const int total4 = B_ * E4;   // 12288
    int i = blockIdx.x * blockDim.x + threadIdx.x;
    if (i >= total4) return;
    const float4* P = reinterpret_cast<const float4*>(part);
    float4 s = P[i];
    for (int sp = 1; sp < nSplit; sp++) {
        float4 v = P[(long)sp * total4 + i];
        s.x += v.x; s.y += v.y; s.z += v.z; s.w += v.w;
    }
    int rr = i / E4;
    int cc = (i - rr * E4) * 4;
    if (bias) {
        float4 b = *(const float4*)(bias + cc);
        s.x += b.x; s.y += b.y; s.z += b.z; s.w += b.w;
    }
    if (Cout) reinterpret_cast<float4*>(Cout)[i] = s;
    if (extOut) {
        __nv_bfloat16* e = extOut + (long)rr * KE + cc;
        st_hilo_pair(e, s.x, s.y);
        st_hilo_pair(e + 2, s.z, s.w);
    }
}

// ================= weight / input converters =================
// prep_ws: one pass over Ws -> g_Wsext (rows) + g_Wstext (transposed), B-mode (hi,hi,lo)
__global__ void __launch_bounds__(256) prep_ws_kernel(
    const float* __restrict__ Ws, __nv_bfloat16* __restrict__ wext,
    __nv_bfloat16* __restrict__ wtext)
{
    __shared__ float tile[32][33];
    int tx = threadIdx.x & 31, ty = threadIdx.x >> 5;  // 32 x 8
    int bx = blockIdx.x * 32, by = blockIdx.y * 32;
#pragma unroll
    for (int j = 0; j < 4; j++) {
        float x = Ws[(long)(by + ty + 8 * j) * E_ + bx + tx];
        tile[ty + 8 * j][tx] = x;
        __nv_bfloat16 h = __float2bfloat16(x);
        __nv_bfloat16 l = __float2bfloat16(x - __bfloat162float(h));
        __nv_bfloat16* o = wext + (long)(by + ty + 8 * j) * KE + bx + tx;
        o[0] = h; o[E_] = h; o[2 * E_] = l;
    }
    __syncthreads();
#pragma unroll
    for (int j = 0; j < 4; j++) {
        float x = tile[tx][ty + 8 * j];
        __nv_bfloat16 h = __float2bfloat16(x);
        __nv_bfloat16 l = __float2bfloat16(x - __bfloat162float(h));
        __nv_bfloat16* o = wtext + (long)(bx + ty + 8 * j) * KE + by + tx;
        o[0] = h; o[E_] = h; o[2 * E_] = l;
    }
}

// batched B-mode convert for Wq / Wv / Wo (z = 0,1,2)
__global__ void __launch_bounds__(256) convB3_kernel(
    const float* __restrict__ s0, const float* __restrict__ s1,
    const float* __restrict__ s2, __nv_bfloat16* __restrict__ d0,
    __nv_bfloat16* __restrict__ d1, __nv_bfloat16* __restrict__ d2)
{
    int i = blockIdx.x * blockDim.x + threadIdx.x;
    if (i >= E_ * E_) return;
    int z = blockIdx.z;
    const float* s = (z == 0) ? s0 : (z == 1) ? s1 : s2;
    __nv_bfloat16* d = (z == 0) ? d0 : (z == 1) ? d1 : d2;
    int rr = i / E_, cc = i - rr * E_;
    float x = s[i];
    __nv_bfloat16 h = __float2bfloat16(x);
    __nv_bfloat16 l = __float2bfloat16(x - __bfloat162float(h));
    __nv_bfloat16* o = d + (long)rr * KE + cc;
    o[0] = h; o[E_] = h; o[2 * E_] = l;
}

// A-mode convert for bio (64 x 768)
__global__ void __launch_bounds__(256) convA_bio_kernel(
    const float* __restrict__ in, __nv_bfloat16* __restrict__ out)
{
    int i = blockIdx.x * blockDim.x + threadIdx.x;
    if (i >= B_ * E_) return;
    int rr = i / E_, cc = i - rr * E_;
    float x = in[i];
    __nv_bfloat16 h = __float2bfloat16(x);
    __nv_bfloat16 l = __float2bfloat16(x - __bfloat162float(h));
    __nv_bfloat16* o = out + (long)rr * KE + cc;
    o[0] = h; o[E_] = l; o[2 * E_] = h;
}

// ================= trilinear sample =================
__global__ void __launch_bounds__(192) sample_kernel(
    const float* __restrict__ x, const float* __restrict__ base,
    const float* __restrict__ off, float* __restrict__ out)
{
    int bp = blockIdx.x;
    int b = bp >> 5, p = bp & 31;

    float cx = fminf(fmaxf(base[p * 3 + 0] + off[bp * 3 + 0], -1.f), 1.f);
    float cy = fminf(fmaxf(base[p * 3 + 1] + off[bp * 3 + 1], -1.f), 1.f);
    float cz = fminf(fmaxf(base[p * 3 + 2] + off[bp * 3 + 2], -1.f), 1.f);

    float ix = (cx + 1.f) * 3.5f;
    float iy = (cy + 1.f) * 3.5f;
    float iz = (cz + 1.f) * 3.5f;
    float fx = floorf(ix), fy = floorf(iy), fz = floorf(iz);
    float wx = ix - fx, wy = iy - fy, wz = iz - fz;
    int x0 = max(0, min(7, (int)fx));
    int y0 = max(0, min(7, (int)fy));
    int z0 = max(0, min(7, (int)fz));
    int x1 = min(7, x0 + 1), y1 = min(7, y0 + 1), z1 = min(7, z0 + 1);

    int r000 = 1 + ((z0 * 8 + y0) * 8 + x0);
    int r001 = 1 + ((z0 * 8 + y0) * 8 + x1);
    int r010 = 1 + ((z0 * 8 + y1) * 8 + x0);
    int r011 = 1 + ((z0 * 8 + y1) * 8 + x1);
    int r100 = 1 + ((z1 * 8 + y0) * 8 + x0);
    int r101 = 1 + ((z1 * 8 + y0) * 8 + x1);
    int r110 = 1 + ((z1 * 8 + y1) * 8 + x0);
    int r111 = 1 + ((z1 * 8 + y1) * 8 + x1);

    float w000 = (1.f - wz) * (1.f - wy) * (1.f - wx);
    float w001 = (1.f - wz) * (1.f - wy) * wx;
    float w010 = (1.f - wz) * wy * (1.f - wx);
    float w011 = (1.f - wz) * wy * wx;
    float w100 = wz * (1.f - wy) * (1.f - wx);
    float w101 = wz * (1.f - wy) * wx;
    float w110 = wz * wy * (1.f - wx);
    float w111 = wz * wy * wx;

    const float4* X = reinterpret_cast<const float4*>(x) + (long)b * FULLN * E4;
    int t = threadIdx.x;
    float4 s = make_float4(0.f, 0.f, 0.f, 0.f);
#define ACC(R, W) { float4 v = X[(R) * E4 + t]; \
        s.x = fmaf(W, v.x, s.x); s.y = fmaf(W, v.y, s.y); \
        s.z = fmaf(W, v.z, s.z); s.w = fmaf(W, v.w, s.w); }
    ACC(r000, w000) ACC(r001, w001) ACC(r010, w010) ACC(r011, w011)
    ACC(r100, w100) ACC(r101, w101) ACC(r110, w110) ACC(r111, w111)
#undef ACC
    reinterpret_cast<float4*>(out)[(long)bp * E4 + t] = s;
}

// ================= step 3: T_h = q_h @ Wk_h (K=64) + ext epilogue ===========
// grid (12 ntiles, 12 heads), 256 threads; SIMT 64x64x64.
__global__ void __launch_bounds__(256) qk_head_kernel(
    const float* __restrict__ q, const float* __restrict__ Wk,
    float* __restrict__ T, __nv_bfloat16* __restrict__ Text)
{
    __shared__ __align__(16) float As[64][68];   // As[k][b]
    __shared__ __align__(16) float Bs[64][68];   // Bs[k][n]
    const int tid = threadIdx.x;
    const int n0 = blockIdx.x * 64;
    const int h = blockIdx.y;

    // FIXED: each thread stages 16 floats (4 x float4) per tile: full 64x64.
    const int r = tid >> 2, cbase = (tid & 3) * 16;
#pragma unroll
    for (int j = 0; j < 4; j++) {
        int c4 = cbase + j * 4;
        // A: q[b = r, h*64 + k = c4..c4+3] -> As[k][b]
        float4 a = *(const float4*)(q + (long)r * E_ + h * HD + c4);
        As[c4 + 0][r] = a.x; As[c4 + 1][r] = a.y;
        As[c4 + 2][r] = a.z; As[c4 + 3][r] = a.w;
        // B: Wk[(h*64 + k = r), n0 + n = c4..c4+3] -> Bs[k][n]
        float4 b = *(const float4*)(Wk + (long)(h * HD + r) * E_ + n0 + c4);
        *(float4*)(&Bs[r][c4]) = b;
    }
    __syncthreads();

    const int ty = tid >> 4, tx = tid & 15;
    float acc[4][4];
#pragma unroll
    for (int i = 0; i < 4; i++)
#pragma unroll
        for (int j = 0; j < 4; j++) acc[i][j] = 0.f;

#pragma unroll 8
    for (int k = 0; k < 64; k++) {
        float4 av = *(const float4*)(&As[k][ty * 4]);
        float4 bv = *(const float4*)(&Bs[k][tx * 4]);
        float a[4] = {av.x, av.y, av.z, av.w};
        float b[4] = {bv.x, bv.y, bv.z, bv.w};
#pragma unroll
        for (int i = 0; i < 4; i++)
#pragma unroll
            for (int j = 0; j < 4; j++)
                acc[i][j] = fmaf(a[i], b[j], acc[i][j]);
    }

#pragma unroll
    for (int i = 0; i < 4; i++) {
        int b = ty * 4 + i;
        long bh = (long)b * H_ + h;
#pragma unroll
        for (int j = 0; j < 4; j += 2) {
            int n = n0 + tx * 4 + j;
            float x0 = acc[i][j], x1 = acc[i][j + 1];
            *(float2*)(T + bh * E_ + n) = make_float2(x0, x1);
            st_hilo_pair(Text + bh * KE + n, x0, x1);
        }
    }
}

// ================= scores + softmax =================
__global__ void __launch_bounds__(128) scores_softmax_kernel(
    const float* __restrict__ TK, const float* __restrict__ T,
    const float* __restrict__ q, const float* __restrict__ sampled,
    const float* __restrict__ in_proj_b, const float* __restrict__ bs,
    float* __restrict__ attn)
{
    int bh = blockIdx.x;
    int b = bh / H_, h = bh % H_;
    __shared__ float tk[E_];
    __shared__ float sc[NB];
    __shared__ float red[4];
    __shared__ float cbs;
    int tid = threadIdx.x;
    int w = tid >> 5, lane = tid & 31;

    const float* TKrow = TK + (long)bh * E_;
    const float* Trow  = T + (long)bh * E_;
    float part = 0.f;
    for (int f = tid; f < E_; f += 128) {
        float t = TKrow[f];
        tk[f] = t;
        part += Trow[f] * bs[f];
    }
    if (tid < HD)
        part += q[(long)b * E_ + h * HD + tid] * in_proj_b[E_ + h * HD + tid];
#pragma unroll
    for (int o = 16; o; o >>= 1) part += __shfl_xor_sync(0xffffffffu, part, o);
    if (lane == 0) red[w] = part;
    __syncthreads();
    if (tid == 0) cbs = red[0] + red[1] + red[2] + red[3];
    __syncthreads();

    float cb = cbs;
#pragma unroll
    for (int pi = 0; pi < 8; pi++) {
        int p = w * 8 + pi;
        const float* srow = sampled + ((long)b * NB + p) * E_;
        float d = 0.f;
        for (int f = lane; f < E_; f += 32) d = fmaf(tk[f], srow[f], d);
#pragma unroll
        for (int o = 16; o; o >>= 1) d += __shfl_xor_sync(0xffffffffu, d, o);
        if (lane == 0) sc[p] = (d + cb) * 0.125f;
    }
    __syncthreads();
    if (tid < NB) {
        float s = sc[tid];
        float m = s;
#pragma unroll
        for (int o = 16; o; o >>= 1) m = fmaxf(m, __shfl_xor_sync(0xffffffffu, m, o));
        float e = expf(s - m);
        float sum = e;
#pragma unroll
        for (int o = 16; o; o >>= 1) sum += __shfl_xor_sync(0xffffffffu, sum, o);
        attn[(long)bh * NB + tid] = e / sum;
    }
}

// ================= US (ext output only) =================
__global__ void __launch_bounds__(192) us_ext_kernel(
    const float* __restrict__ attn, const float* __restrict__ sampled,
    __nv_bfloat16* __restrict__ ext)
{
    int bh = blockIdx.x;
    int b = bh / H_;
    __shared__ float a[NB];
    if (threadIdx.x < NB) a[threadIdx.x] = attn[(long)bh * NB + threadIdx.x];
    __syncthreads();
    int t = threadIdx.x;
    const float4* S = reinterpret_cast<const float4*>(sampled) + (long)b * NB * E4;
    float4 acc = make_float4(0.f, 0.f, 0.f, 0.f);
#pragma unroll 8
    for (int p = 0; p < NB; p++) {
        float wv = a[p];
        float4 s = S[p * E4 + t];
        acc.x = fmaf(wv, s.x, acc.x); acc.y = fmaf(wv, s.y, acc.y);
        acc.z = fmaf(wv, s.z, acc.z); acc.w = fmaf(wv, s.w, acc.w);
    }
    __nv_bfloat16* e = ext + (long)bh * KE + 4 * t;
    st_hilo_pair(e, acc.x, acc.y);
    st_hilo_pair(e + 2, acc.z, acc.w);
}

// ================= broadcast out =================
__global__ void __launch_bounds__(192) out_kernel(
    const float* __restrict__ ao, const float* __restrict__ conf,
    float4* __restrict__ out)
{
    int b = blockIdx.y, n = blockIdx.x, t = threadIdx.x;
    float s = conf[b];
    float4 v = reinterpret_cast<const float4*>(ao)[b * E4 + t];
    v.x *= s; v.y *= s; v.z *= s; v.w *= s;
    out[((long)b * FULLN + n) * E4 + t] = v;
}

// ================================================================
extern "C" void kernel_launch(void* const* d_in, const int* in_sizes, int n_in,
                              void* d_out, int out_size)
{
    const float* x    = (const float*)d_in[0];
    const float* bio  = (const float*)d_in[1];
    const float* base = (const float*)d_in[2];
    const float* off  = (const float*)d_in[3];
    const float* conf = (const float*)d_in[4];
    const float* Ws   = (const float*)d_in[5];
    const float* bs   = (const float*)d_in[6];
    const float* Win  = (const float*)d_in[7];
    const float* bin  = (const float*)d_in[8];
    const float* Wo   = (const float*)d_in[9];
    const float* bo   = (const float*)d_in[10];
    float* out = (float*)d_out;

    float *sampled, *q, *T, *TK, *attn, *ao, *part;
    cudaGetSymbolAddress((void**)&sampled, g_sampled);
    cudaGetSymbolAddress((void**)&q,    g_q);
    cudaGetSymbolAddress((void**)&T,    g_T);
    cudaGetSymbolAddress((void**)&TK,   g_TK);
    cudaGetSymbolAddress((void**)&attn, g_attn);
    cudaGetSymbolAddress((void**)&ao,   g_ao);
    cudaGetSymbolAddress((void**)&part, g_part);

    __nv_bfloat16 *ext1, *Uext, *Wsext, *Wstext, *Wq, *Wv, *Wox, *bioext, *ctxext;
    cudaGetSymbolAddress((void**)&ext1,   g_ext1);
    cudaGetSymbolAddress((void**)&Uext,   g_Uext);
    cudaGetSymbolAddress((void**)&Wsext,  g_Wsext);
    cudaGetSymbolAddress((void**)&Wstext, g_Wstext);
    cudaGetSymbolAddress((void**)&Wq,     g_Wq);
    cudaGetSymbolAddress((void**)&Wv,     g_Wv);
    cudaGetSymbolAddress((void**)&Wox,    g_Wo);
    cudaGetSymbolAddress((void**)&bioext, g_bioext);
    cudaGetSymbolAddress((void**)&ctxext, g_ctxext);

    const long spl = (long)B_ * E_;   // split stride for skinny partials

    // 1) trilinear sample
    sample_kernel<<<B_ * NB, 192>>>(x, base, off, sampled);

    // 2) weight/input conversions (independent of sample)
    prep_ws_kernel<<<dim3(24, 24), 256>>>(Ws, Wsext, Wstext);
    convB3_kernel<<<dim3((E_ * E_ + 255) / 256, 1, 3), 256>>>(
        Win, Win + 2 * E_ * E_, Wo, Wq, Wv, Wox);
    convA_bio_kernel<<<(B_ * E_ + 255) / 256, 256>>>(bio, bioext);

    // 3) q = bio @ Wq.T + bq   (skinny HMMA, split-K=4)
    hmma_kernel<<<dim3(12, 1, 4), 256>>>(
        bioext, KE, 0, Wq, 0, nullptr, part, nullptr, 0, 4, 576, spl);
    reduce2_kernel<<<48, 256>>>(part, bin, q, nullptr, 4);

    // 4) T_h = q_h @ Wk_h  -> T fp32 + T ext
    qk_head_kernel<<<dim3(12, H_), 256>>>(q, Win + E_ * E_, T, ext1);

    // 5) TK = T @ Ws  (big HMMA)
    hmma_kernel<<<dim3(12, 12, 1), 256>>>(
        ext1, KE, 0, Wstext, 0, nullptr, TK, nullptr, 0, 1, KE, 0);

    // 6) scores + softmax
    scores_softmax_kernel<<<BH, 128>>>(TK, T, q, sampled, bin, bs, attn);

    // 7) US -> ext directly
    us_ext_kernel<<<BH, 192>>>(attn, sampled, ext1);

    // 8) U = US @ Ws.T + bs  (big HMMA) -> U ext only
    hmma_kernel<<<dim3(12, 12, 1), 256>>>(
        ext1, KE, 0, Wsext, 0, bs, nullptr, Uext, 0, 1, KE, 0);

    // 9) ctx_h = U_h @ Wv_h.T + bv  (batched skinny HMMA, z = head*4+split)
    hmma_kernel<<<dim3(1, 1, H_ * 4), 256>>>(
        Uext, (long)H_ * KE, KE, Wv, (long)HD * KE, nullptr, part, nullptr,
        HD, 4, 576, spl);
    reduce2_kernel<<<48, 256>>>(part, bin + 2 * E_, nullptr, ctxext, 4);

    // 10) attn_out = ctx @ Wo.T + bo  (skinny HMMA)
    hmma_kernel<<<dim3(12, 1, 4), 256>>>(
        ctxext, KE, 0, Wox, 0, nullptr, part, nullptr, 0, 4, 576, spl);
    reduce2_kernel<<<48, 256>>>(part, bo, ao, nullptr, 4);

    // 11) broadcast * confidence
    out_kernel<<<dim3(FULLN, B_), 192>>>(ao, conf, (float4*)out);
}